// round 12
// baseline (speedup 1.0000x reference)
#include <cuda_runtime.h>
#include <cuda_fp16.h>

#define BB   1024
#define FF   39
#define KK   16
#define PP   741
#define PPP  768                      // padded pair stride
#define TT   9139
#define TTP  9216                     // padded triple stride (36*256)
#define SE   20                       // embedding row stride (floats)
#define NTHR 256
#define BSPLIT 16                     // batch split for stats
#define TSPLIT 4                      // T split for final reduce
#define TCHUNK (TTP / TSPLIT)         // 2304
#define SCALE  65536.0f               // exact 2^16 scaling for fp16 storage

// ---- device-global scratch (no allocations allowed; zero-init at load,
//      padding regions are never written so they stay 0) ----
__device__ __align__(16) float  g_L2[BB * PPP];           // ~3.1 MB fp32
__device__ __align__(16) __half g_L3h[(size_t)BB * TTP];  // ~18.9 MB fp16 (x * 2^16)
__device__ float g_lin[BB];
__device__ __align__(16) float g_c2[PPP];    // pad stays 0
__device__ __align__(16) float g_c3[TTP];    // pad stays 0 (1/2^16 folded in)
__device__ float g_ps3[BSPLIT][TTP], g_pq3[BSPLIT][TTP];  // per-split partials
__device__ float g_ps2[BSPLIT][PPP], g_pq2[BSPLIT][PPP];
__device__ int   g_qdec[PP];                 // a | (b2<<8), canonical pair order
__device__ float g_g2[PP], g_b2p[PP], g_w2[PP];   // BN params permuted canonical
__device__ float g_g3[TT], g_b3p[TT], g_w3[TT];
__device__ float g_sumo;
__device__ float g_facc[BB];

// ---------------------------------------------------------------------------
// Kernel 0: canonical orderings + permuted BN params; zero atomic targets
//   pair  (a,b2):   q  = b2(b2-1)/2 + a      (b2-major)
//   triple(a,b2,c): tc = C(c,3) + q
// ---------------------------------------------------------------------------
__global__ void pack_tri(const int* __restrict__ i1, const int* __restrict__ i2,
                         const int* __restrict__ i3,
                         const int* __restrict__ rows, const int* __restrict__ cols,
                         const float* __restrict__ gamma2, const float* __restrict__ beta2,
                         const float* __restrict__ gw2,
                         const float* __restrict__ gamma3, const float* __restrict__ beta3,
                         const float* __restrict__ gw3) {
    int t = blockIdx.x * blockDim.x + threadIdx.x;
    if (t < TT) {
        int a = i1[t], b2 = i2[t], c = i3[t];
        int tc = (c * (c - 1) * (c - 2)) / 6 + (b2 * (b2 - 1)) / 2 + a;
        g_g3[tc]  = gamma3[t];
        g_b3p[tc] = beta3[t];
        g_w3[tc]  = gw3[t];
    }
    if (t < PP) {
        int r = rows[t], cl = cols[t];            // r > cl
        int q = (r * (r - 1)) / 2 + cl;
        g_qdec[q] = cl | (r << 8);
        g_g2[q]  = gamma2[t];
        g_b2p[q] = beta2[t];
        g_w2[q]  = gw2[t];
    }
    if (t < BB) g_facc[t] = 0.f;
    if (t == 0) g_sumo = 0.f;
}

// ---------------------------------------------------------------------------
// Kernel A: per-batch-row gather + level2 (fp32) + level3 (fp16, x*2^16)
// ---------------------------------------------------------------------------
__global__ __launch_bounds__(NTHR) void compute_levels(
    const int*   __restrict__ feats,
    const float* __restrict__ w,
    const float* __restrict__ v)
{
    __shared__ float sxv[FF * SE];
    __shared__ int   sidx[FF];

    const int b   = blockIdx.x;
    const int tid = threadIdx.x;

    if (tid < FF) sidx[tid] = feats[b * FF + tid];
    __syncthreads();

    for (int e = tid; e < FF * KK; e += NTHR) {
        int f = e >> 4, k = e & 15;
        sxv[f * SE + k] = v[(size_t)sidx[f] * KK + k];
    }
    if (tid < 32) {
        float s = 0.f;
        for (int f = tid; f < FF; f += 32) s += w[sidx[f]];
        #pragma unroll
        for (int o = 16; o; o >>= 1) s += __shfl_down_sync(0xffffffffu, s, o);
        if (tid == 0) g_lin[b] = s;
    }
    __syncthreads();

    __half* dst = g_L3h + (size_t)b * TTP;

    for (int q = tid; q < PP; q += NTHR) {
        int d  = __ldg(&g_qdec[q]);
        int a  = d & 255, b2 = d >> 8;
        const float4* ea = (const float4*)&sxv[a * SE];
        const float4* eb = (const float4*)&sxv[b2 * SE];

        float4 p0, p1, p2, p3;
        {
            float4 x, y;
            x = ea[0]; y = eb[0];
            p0.x = x.x*y.x; p0.y = x.y*y.y; p0.z = x.z*y.z; p0.w = x.w*y.w;
            x = ea[1]; y = eb[1];
            p1.x = x.x*y.x; p1.y = x.y*y.y; p1.z = x.z*y.z; p1.w = x.w*y.w;
            x = ea[2]; y = eb[2];
            p2.x = x.x*y.x; p2.y = x.y*y.y; p2.z = x.z*y.z; p2.w = x.w*y.w;
            x = ea[3]; y = eb[3];
            p3.x = x.x*y.x; p3.y = x.y*y.y; p3.z = x.z*y.z; p3.w = x.w*y.w;
        }
        g_L2[b * PPP + q] = (p0.x+p0.y+p0.z+p0.w) + (p1.x+p1.y+p1.z+p1.w)
                          + (p2.x+p2.y+p2.z+p2.w) + (p3.x+p3.y+p3.z+p3.w);

        int c0   = b2 + 1;
        int base = (c0 * (c0 - 1) * (c0 - 2)) / 6;
        int inc  = (c0 * (c0 - 1)) / 2;
        for (int c = c0; c < FF; c++) {
            const float4* ec = (const float4*)&sxv[c * SE];   // broadcast
            float4 e0 = ec[0], e1 = ec[1], e2 = ec[2], e3 = ec[3];
            float s0 = p0.x*e0.x + p0.y*e0.y + p0.z*e0.z + p0.w*e0.w;
            float s1 = p1.x*e1.x + p1.y*e1.y + p1.z*e1.z + p1.w*e1.w;
            float s2 = p2.x*e2.x + p2.y*e2.y + p2.z*e2.z + p2.w*e2.w;
            float s3 = p3.x*e3.x + p3.y*e3.y + p3.z*e3.z + p3.w*e3.w;
            dst[base + q] = __float2half_rn(((s0 + s1) + (s2 + s3)) * SCALE);
            base += inc;
            inc  += c;
        }
    }
}

// ---------------------------------------------------------------------------
// Kernel B: fused batch-split column stats (L3 fp16 + L2 fp32), NO atomics.
// grid (36+3, BSPLIT). Each tx owns 8 consecutive columns; 64 rows per split.
// ---------------------------------------------------------------------------
__global__ __launch_bounds__(NTHR) void stats_acc()
{
    __shared__ float shs[8][NTHR], shq[8][NTHR];
    const int tx = threadIdx.x & 31;
    const int ty = threadIdx.x >> 5;
    const int split = blockIdx.y;
    const int b0 = split * (BB / BSPLIT);     // 64 rows

    float s[8], q[8];
    #pragma unroll
    for (int e = 0; e < 8; e++) { s[e] = 0.f; q[e] = 0.f; }

    if (blockIdx.x < TTP / 256) {
        const int t0 = blockIdx.x * 256 + tx * 8;
        for (int i = ty; i < BB / BSPLIT; i += 8) {
            uint4 h = *(const uint4*)(g_L3h + (size_t)(b0 + i) * TTP + t0);
            const __half2* hp = (const __half2*)&h;
            #pragma unroll
            for (int e = 0; e < 4; e++) {
                float2 f = __half22float2(hp[e]);
                s[2*e]   += f.x; q[2*e]   += f.x * f.x;
                s[2*e+1] += f.y; q[2*e+1] += f.y * f.y;
            }
        }
        #pragma unroll
        for (int e = 0; e < 8; e++) { shs[ty][tx*8+e] = s[e]; shq[ty][tx*8+e] = q[e]; }
        __syncthreads();
        int col = threadIdx.x;
        float S = 0.f, Q = 0.f;
        #pragma unroll
        for (int j = 0; j < 8; j++) { S += shs[j][col]; Q += shq[j][col]; }
        g_ps3[split][blockIdx.x * 256 + col] = S;
        g_pq3[split][blockIdx.x * 256 + col] = Q;
    } else {
        const int p0 = (blockIdx.x - TTP / 256) * 256 + tx * 8;
        for (int i = ty; i < BB / BSPLIT; i += 8) {
            const float4* xp = (const float4*)(g_L2 + (b0 + i) * PPP + p0);
            float4 x = xp[0], y = xp[1];
            s[0]+=x.x; q[0]+=x.x*x.x;  s[1]+=x.y; q[1]+=x.y*x.y;
            s[2]+=x.z; q[2]+=x.z*x.z;  s[3]+=x.w; q[3]+=x.w*x.w;
            s[4]+=y.x; q[4]+=y.x*y.x;  s[5]+=y.y; q[5]+=y.y*y.y;
            s[6]+=y.z; q[6]+=y.z*y.z;  s[7]+=y.w; q[7]+=y.w*y.w;
        }
        #pragma unroll
        for (int e = 0; e < 8; e++) { shs[ty][tx*8+e] = s[e]; shq[ty][tx*8+e] = q[e]; }
        __syncthreads();
        int col = threadIdx.x;
        float S = 0.f, Q = 0.f;
        #pragma unroll
        for (int j = 0; j < 8; j++) { S += shs[j][col]; Q += shq[j][col]; }
        g_ps2[split][(blockIdx.x - TTP / 256) * 256 + col] = S;
        g_pq2[split][(blockIdx.x - TTP / 256) * 256 + col] = Q;
    }
}

// ---------------------------------------------------------------------------
// Kernel C: sum partials -> affine coefficients; accumulate Sum(o).
// 4 THREADS PER COLUMN (sub-split over the 16 partials) + shfl combine.
// grid.x = TTP/64 + PPP/64 = 144 + 12 = 156 CTAs (no warp straddles branches).
// ---------------------------------------------------------------------------
__global__ __launch_bounds__(NTHR) void finalize()
{
    const int tid = threadIdx.x;
    const int sub = tid & 3;               // which 4-of-16 splits
    const int colL = tid >> 2;             // 0..63
    float osum = 0.f;

    if (blockIdx.x < TTP / 64) {
        const int t = blockIdx.x * 64 + colL;
        float S = 0.f, Q = 0.f;
        #pragma unroll
        for (int j = 0; j < 4; j++) {
            int sp = sub * 4 + j;
            S += g_ps3[sp][t];
            Q += g_pq3[sp][t];
        }
        S += __shfl_xor_sync(0xffffffffu, S, 1);
        Q += __shfl_xor_sync(0xffffffffu, Q, 1);
        S += __shfl_xor_sync(0xffffffffu, S, 2);
        Q += __shfl_xor_sync(0xffffffffu, Q, 2);
        if (sub == 0 && t < TT) {
            float mean_s = S * (1.0f / BB);                       // scaled mean
            float var_s  = Q * (1.0f / BB) - mean_s * mean_s;     // scaled^2 var
            float inv    = rsqrtf(var_s * (1.0f / (SCALE * SCALE)) + 1e-3f);
            float c_true = g_g3[t] * g_w3[t] * inv;
            float c3p    = c_true * (1.0f / SCALE);
            g_c3[t] = c3p;
            osum = g_b3p[t] * g_w3[t] - c3p * mean_s;             // c_true*mean_true
        }
    } else {
        const int p = (blockIdx.x - TTP / 64) * 64 + colL;
        float S = 0.f, Q = 0.f;
        #pragma unroll
        for (int j = 0; j < 4; j++) {
            int sp = sub * 4 + j;
            S += g_ps2[sp][p];
            Q += g_pq2[sp][p];
        }
        S += __shfl_xor_sync(0xffffffffu, S, 1);
        Q += __shfl_xor_sync(0xffffffffu, Q, 1);
        S += __shfl_xor_sync(0xffffffffu, S, 2);
        Q += __shfl_xor_sync(0xffffffffu, Q, 2);
        if (sub == 0 && p < PP) {
            float mean = S * (1.0f / BB);
            float var  = Q * (1.0f / BB) - mean * mean;
            float inv  = rsqrtf(var + 1e-3f);
            float cc   = g_g2[p] * g_w2[p] * inv;
            g_c2[p] = cc;
            osum = g_b2p[p] * g_w2[p] - cc * mean;
        }
    }

    #pragma unroll
    for (int o = 16; o; o >>= 1) osum += __shfl_down_sync(0xffffffffu, osum, o);
    __shared__ float red[8];
    if ((tid & 31) == 0) red[tid >> 5] = osum;
    __syncthreads();
    if (tid == 0) {
        float s = 0.f;
        #pragma unroll
        for (int j = 0; j < 8; j++) s += red[j];
        atomicAdd(&g_sumo, s);
    }
}

// ---------------------------------------------------------------------------
// Kernel D: weighted reductions. 8 b-rows per CTA, T split 4-way.
// L3 read as half8 (uint4); pad columns: c3=0 and L3h=0 -> safe.
// ---------------------------------------------------------------------------
__global__ __launch_bounds__(NTHR) void final_reduce()
{
    const int b0  = blockIdx.x * 8;
    const int tid = threadIdx.x;
    const int tlo = blockIdx.y * TCHUNK;
    const int thi = tlo + TCHUNK;
    float acc[8] = {0.f, 0.f, 0.f, 0.f, 0.f, 0.f, 0.f, 0.f};

    for (int t = tlo + tid * 8; t < thi; t += NTHR * 8) {
        float4 c0 = *(const float4*)&g_c3[t];
        float4 c1 = *(const float4*)&g_c3[t + 4];
        const __half* base = g_L3h + (size_t)b0 * TTP + t;
        #pragma unroll
        for (int j = 0; j < 8; j++) {
            uint4 h = *(const uint4*)(base + (size_t)j * TTP);
            const __half2* hp = (const __half2*)&h;
            float2 f0 = __half22float2(hp[0]), f1 = __half22float2(hp[1]);
            float2 f2 = __half22float2(hp[2]), f3 = __half22float2(hp[3]);
            acc[j] += c0.x*f0.x + c0.y*f0.y + c0.z*f1.x + c0.w*f1.y
                    + c1.x*f2.x + c1.y*f2.y + c1.z*f3.x + c1.w*f3.y;
        }
    }
    if (blockIdx.y == 0) {
        for (int p = tid * 4; p < PPP; p += NTHR * 4) {
            float4 c = *(const float4*)&g_c2[p];
            const float* base = g_L2 + b0 * PPP + p;
            #pragma unroll
            for (int j = 0; j < 8; j++) {
                float4 x = *(const float4*)(base + j * PPP);
                acc[j] += c.x * x.x + c.y * x.y + c.z * x.z + c.w * x.w;
            }
        }
    }

    __shared__ float red[8][8];   // [warp][j]
    #pragma unroll
    for (int j = 0; j < 8; j++) {
        float vsum = acc[j];
        #pragma unroll
        for (int o = 16; o; o >>= 1) vsum += __shfl_down_sync(0xffffffffu, vsum, o);
        if ((tid & 31) == 0) red[tid >> 5][j] = vsum;
    }
    __syncthreads();
    if (tid < 8) {
        float s = 0.f;
        #pragma unroll
        for (int wp = 0; wp < 8; wp++) s += red[wp][tid];
        atomicAdd(&g_facc[b0 + tid], s);
    }
}

// ---------------------------------------------------------------------------
// Kernel E: epilogue -> logits
// ---------------------------------------------------------------------------
__global__ void epilogue(const float* __restrict__ bias, float* __restrict__ out)
{
    int b = blockIdx.x * blockDim.x + threadIdx.x;
    if (b < BB) out[b] = g_facc[b] + g_lin[b] + bias[0] + g_sumo;
}

// ---------------------------------------------------------------------------
extern "C" void kernel_launch(void* const* d_in, const int* in_sizes, int n_in,
                              void* d_out, int out_size)
{
    const int*   feats  = (const int*)  d_in[0];
    const float* w      = (const float*)d_in[1];
    const float* v      = (const float*)d_in[2];
    const float* bias   = (const float*)d_in[3];
    const float* gamma2 = (const float*)d_in[4];
    const float* beta2  = (const float*)d_in[5];
    const float* gw2    = (const float*)d_in[6];
    const float* gamma3 = (const float*)d_in[7];
    const float* beta3  = (const float*)d_in[8];
    const float* gw3    = (const float*)d_in[9];
    const int*   rows   = (const int*)  d_in[10];
    const int*   cols   = (const int*)  d_in[11];
    const int*   i1     = (const int*)  d_in[12];
    const int*   i2     = (const int*)  d_in[13];
    const int*   i3     = (const int*)  d_in[14];
    float* out = (float*)d_out;

    pack_tri<<<TTP / NTHR, NTHR>>>(i1, i2, i3, rows, cols,
                                   gamma2, beta2, gw2, gamma3, beta3, gw3);
    compute_levels<<<BB, NTHR>>>(feats, w, v);
    stats_acc<<<dim3(TTP / 256 + PPP / 256, BSPLIT), NTHR>>>();
    finalize<<<TTP / 64 + PPP / 64, NTHR>>>();
    final_reduce<<<dim3(BB / 8, TSPLIT), NTHR>>>();
    epilogue<<<BB / NTHR, NTHR>>>(bias, out);
}

// round 16
// speedup vs baseline: 1.0143x; 1.0143x over previous
#include <cuda_runtime.h>
#include <cuda_fp16.h>

#define BB   1024
#define FF   39
#define KK   16
#define PP   741
#define PPP  768                      // padded pair stride
#define TT   9139
#define TTP  9216                     // padded triple stride (36*256)
#define SE   20                       // embedding row stride (floats)
#define NTHR 256
#define BSPLIT 16                     // batch split for stats
#define NXB  (TTP / 256 + PPP / 256)  // 39 x-blocks (36 L3 + 3 L2)
#define SCALE  65536.0f               // exact 2^16 scaling for fp16 storage

// ---- device-global scratch (no allocations allowed; zero-init at load,
//      padding regions are never written so they stay 0) ----
__device__ __align__(16) float  g_L2[BB * PPP];           // ~3.1 MB fp32
__device__ __align__(16) __half g_L3h[(size_t)BB * TTP];  // ~18.9 MB fp16 (x * 2^16)
__device__ float g_lin[BB];
__device__ __align__(16) float g_c2[PPP];    // pad stays 0
__device__ __align__(16) float g_c3[TTP];    // pad stays 0 (1/2^16 folded in)
__device__ float g_ps3[BSPLIT][TTP], g_pq3[BSPLIT][TTP];  // per-split partials
__device__ float g_ps2[BSPLIT][PPP], g_pq2[BSPLIT][PPP];
__device__ int   g_qdec[PP];                 // a | (b2<<8), canonical pair order
__device__ float g_g2[PP], g_b2p[PP], g_w2[PP];   // BN params permuted canonical
__device__ float g_g3[TT], g_b3p[TT], g_w3[TT];
__device__ int   g_cnt[NXB];                 // per-x-block completion counters
__device__ float g_sumo;

// ---------------------------------------------------------------------------
// Kernel 0: canonical orderings + permuted BN params; reset counters/sumo
//   pair  (a,b2):   q  = b2(b2-1)/2 + a      (b2-major)
//   triple(a,b2,c): tc = C(c,3) + q
// ---------------------------------------------------------------------------
__global__ void pack_tri(const int* __restrict__ i1, const int* __restrict__ i2,
                         const int* __restrict__ i3,
                         const int* __restrict__ rows, const int* __restrict__ cols,
                         const float* __restrict__ gamma2, const float* __restrict__ beta2,
                         const float* __restrict__ gw2,
                         const float* __restrict__ gamma3, const float* __restrict__ beta3,
                         const float* __restrict__ gw3) {
    int t = blockIdx.x * blockDim.x + threadIdx.x;
    if (t < TT) {
        int a = i1[t], b2 = i2[t], c = i3[t];
        int tc = (c * (c - 1) * (c - 2)) / 6 + (b2 * (b2 - 1)) / 2 + a;
        g_g3[tc]  = gamma3[t];
        g_b3p[tc] = beta3[t];
        g_w3[tc]  = gw3[t];
    }
    if (t < PP) {
        int r = rows[t], cl = cols[t];            // r > cl
        int q = (r * (r - 1)) / 2 + cl;
        g_qdec[q] = cl | (r << 8);
        g_g2[q]  = gamma2[t];
        g_b2p[q] = beta2[t];
        g_w2[q]  = gw2[t];
    }
    if (t < NXB) g_cnt[t] = 0;
    if (t == 0)  g_sumo = 0.f;
}

// ---------------------------------------------------------------------------
// Kernel A: per-batch-row gather + level2 (fp32) + level3 (fp16, x*2^16)
// ---------------------------------------------------------------------------
__global__ __launch_bounds__(NTHR) void compute_levels(
    const int*   __restrict__ feats,
    const float* __restrict__ w,
    const float* __restrict__ v)
{
    __shared__ float sxv[FF * SE];
    __shared__ int   sidx[FF];

    const int b   = blockIdx.x;
    const int tid = threadIdx.x;

    if (tid < FF) sidx[tid] = feats[b * FF + tid];
    __syncthreads();

    for (int e = tid; e < FF * KK; e += NTHR) {
        int f = e >> 4, k = e & 15;
        sxv[f * SE + k] = v[(size_t)sidx[f] * KK + k];
    }
    if (tid < 32) {
        float s = 0.f;
        for (int f = tid; f < FF; f += 32) s += w[sidx[f]];
        #pragma unroll
        for (int o = 16; o; o >>= 1) s += __shfl_down_sync(0xffffffffu, s, o);
        if (tid == 0) g_lin[b] = s;
    }
    __syncthreads();

    __half* dst = g_L3h + (size_t)b * TTP;

    for (int q = tid; q < PP; q += NTHR) {
        int d  = __ldg(&g_qdec[q]);
        int a  = d & 255, b2 = d >> 8;
        const float4* ea = (const float4*)&sxv[a * SE];
        const float4* eb = (const float4*)&sxv[b2 * SE];

        float4 p0, p1, p2, p3;
        {
            float4 x, y;
            x = ea[0]; y = eb[0];
            p0.x = x.x*y.x; p0.y = x.y*y.y; p0.z = x.z*y.z; p0.w = x.w*y.w;
            x = ea[1]; y = eb[1];
            p1.x = x.x*y.x; p1.y = x.y*y.y; p1.z = x.z*y.z; p1.w = x.w*y.w;
            x = ea[2]; y = eb[2];
            p2.x = x.x*y.x; p2.y = x.y*y.y; p2.z = x.z*y.z; p2.w = x.w*y.w;
            x = ea[3]; y = eb[3];
            p3.x = x.x*y.x; p3.y = x.y*y.y; p3.z = x.z*y.z; p3.w = x.w*y.w;
        }
        g_L2[b * PPP + q] = (p0.x+p0.y+p0.z+p0.w) + (p1.x+p1.y+p1.z+p1.w)
                          + (p2.x+p2.y+p2.z+p2.w) + (p3.x+p3.y+p3.z+p3.w);

        int c0   = b2 + 1;
        int base = (c0 * (c0 - 1) * (c0 - 2)) / 6;
        int inc  = (c0 * (c0 - 1)) / 2;
        for (int c = c0; c < FF; c++) {
            const float4* ec = (const float4*)&sxv[c * SE];   // broadcast
            float4 e0 = ec[0], e1 = ec[1], e2 = ec[2], e3 = ec[3];
            float s0 = p0.x*e0.x + p0.y*e0.y + p0.z*e0.z + p0.w*e0.w;
            float s1 = p1.x*e1.x + p1.y*e1.y + p1.z*e1.z + p1.w*e1.w;
            float s2 = p2.x*e2.x + p2.y*e2.y + p2.z*e2.z + p2.w*e2.w;
            float s3 = p3.x*e3.x + p3.y*e3.y + p3.z*e3.z + p3.w*e3.w;
            dst[base + q] = __float2half_rn(((s0 + s1) + (s2 + s3)) * SCALE);
            base += inc;
            inc  += c;
        }
    }
}

// ---------------------------------------------------------------------------
// Kernel B: fused batch-split column stats + LAST-CTA finalize per x-block.
// grid (NXB, BSPLIT). Each tx owns 8 consecutive columns; 64 rows per split.
// The 16th CTA to finish an x-block sums the 16 partials and emits c/o.
// ---------------------------------------------------------------------------
__global__ __launch_bounds__(NTHR) void stats_acc()
{
    __shared__ float shs[8][NTHR], shq[8][NTHR];
    __shared__ int   s_last;
    const int tx = threadIdx.x & 31;
    const int ty = threadIdx.x >> 5;
    const int split = blockIdx.y;
    const int b0 = split * (BB / BSPLIT);     // 64 rows
    const bool isL3 = blockIdx.x < TTP / 256;

    float s[8], q[8];
    #pragma unroll
    for (int e = 0; e < 8; e++) { s[e] = 0.f; q[e] = 0.f; }

    if (isL3) {
        const int t0 = blockIdx.x * 256 + tx * 8;
        for (int i = ty; i < BB / BSPLIT; i += 8) {
            uint4 h = *(const uint4*)(g_L3h + (size_t)(b0 + i) * TTP + t0);
            const __half2* hp = (const __half2*)&h;
            #pragma unroll
            for (int e = 0; e < 4; e++) {
                float2 f = __half22float2(hp[e]);
                s[2*e]   += f.x; q[2*e]   += f.x * f.x;
                s[2*e+1] += f.y; q[2*e+1] += f.y * f.y;
            }
        }
        #pragma unroll
        for (int e = 0; e < 8; e++) { shs[ty][tx*8+e] = s[e]; shq[ty][tx*8+e] = q[e]; }
        __syncthreads();
        int col = threadIdx.x;
        float S = 0.f, Q = 0.f;
        #pragma unroll
        for (int j = 0; j < 8; j++) { S += shs[j][col]; Q += shq[j][col]; }
        g_ps3[split][blockIdx.x * 256 + col] = S;
        g_pq3[split][blockIdx.x * 256 + col] = Q;
    } else {
        const int p0 = (blockIdx.x - TTP / 256) * 256 + tx * 8;
        for (int i = ty; i < BB / BSPLIT; i += 8) {
            const float4* xp = (const float4*)(g_L2 + (b0 + i) * PPP + p0);
            float4 x = xp[0], y = xp[1];
            s[0]+=x.x; q[0]+=x.x*x.x;  s[1]+=x.y; q[1]+=x.y*x.y;
            s[2]+=x.z; q[2]+=x.z*x.z;  s[3]+=x.w; q[3]+=x.w*x.w;
            s[4]+=y.x; q[4]+=y.x*y.x;  s[5]+=y.y; q[5]+=y.y*y.y;
            s[6]+=y.z; q[6]+=y.z*y.z;  s[7]+=y.w; q[7]+=y.w*y.w;
        }
        #pragma unroll
        for (int e = 0; e < 8; e++) { shs[ty][tx*8+e] = s[e]; shq[ty][tx*8+e] = q[e]; }
        __syncthreads();
        int col = threadIdx.x;
        float S = 0.f, Q = 0.f;
        #pragma unroll
        for (int j = 0; j < 8; j++) { S += shs[j][col]; Q += shq[j][col]; }
        g_ps2[split][(blockIdx.x - TTP / 256) * 256 + col] = S;
        g_pq2[split][(blockIdx.x - TTP / 256) * 256 + col] = Q;
    }

    // ---- last-CTA-done finalize for this x-block ----
    __threadfence();
    if (threadIdx.x == 0)
        s_last = (atomicAdd(&g_cnt[blockIdx.x], 1) == BSPLIT - 1);
    __syncthreads();
    if (!s_last) return;
    __threadfence();   // make other CTAs' partials visible

    float osum = 0.f;
    if (isL3) {
        const int t = blockIdx.x * 256 + threadIdx.x;
        float S = 0.f, Q = 0.f;
        #pragma unroll
        for (int sp = 0; sp < BSPLIT; sp++) { S += g_ps3[sp][t]; Q += g_pq3[sp][t]; }
        if (t < TT) {
            float mean_s = S * (1.0f / BB);                       // scaled mean
            float var_s  = Q * (1.0f / BB) - mean_s * mean_s;     // scaled^2 var
            float inv    = rsqrtf(var_s * (1.0f / (SCALE * SCALE)) + 1e-3f);
            float c_true = g_g3[t] * g_w3[t] * inv;
            float c3p    = c_true * (1.0f / SCALE);
            g_c3[t] = c3p;
            osum = g_b3p[t] * g_w3[t] - c3p * mean_s;             // c_true*mean_true
        }
    } else {
        const int p = (blockIdx.x - TTP / 256) * 256 + threadIdx.x;
        float S = 0.f, Q = 0.f;
        #pragma unroll
        for (int sp = 0; sp < BSPLIT; sp++) { S += g_ps2[sp][p]; Q += g_pq2[sp][p]; }
        if (p < PP) {
            float mean = S * (1.0f / BB);
            float var  = Q * (1.0f / BB) - mean * mean;
            float inv  = rsqrtf(var + 1e-3f);
            float cc   = g_g2[p] * g_w2[p] * inv;
            g_c2[p] = cc;
            osum = g_b2p[p] * g_w2[p] - cc * mean;
        }
    }
    #pragma unroll
    for (int o = 16; o; o >>= 1) osum += __shfl_down_sync(0xffffffffu, osum, o);
    if ((threadIdx.x & 31) == 0) shs[0][threadIdx.x >> 5] = osum;
    __syncthreads();
    if (threadIdx.x == 0) {
        float t2 = 0.f;
        #pragma unroll
        for (int j = 0; j < 8; j++) t2 += shs[0][j];
        atomicAdd(&g_sumo, t2);
    }
}

// ---------------------------------------------------------------------------
// Kernel C: weighted reductions + epilogue. grid 128, 8 b-rows per CTA,
// full T+P range per CTA, direct out write (no atomics, no extra kernel).
// Pad columns: c3=0 and L3h=0 -> guard-free half8/float4 loads.
// ---------------------------------------------------------------------------
__global__ __launch_bounds__(NTHR) void final_reduce(
    const float* __restrict__ bias, float* __restrict__ out)
{
    const int b0  = blockIdx.x * 8;
    const int tid = threadIdx.x;
    float acc[8] = {0.f, 0.f, 0.f, 0.f, 0.f, 0.f, 0.f, 0.f};

    for (int t = tid * 8; t < TTP; t += NTHR * 8) {
        float4 c0 = *(const float4*)&g_c3[t];
        float4 c1 = *(const float4*)&g_c3[t + 4];
        const __half* base = g_L3h + (size_t)b0 * TTP + t;
        #pragma unroll
        for (int j = 0; j < 8; j++) {
            uint4 h = *(const uint4*)(base + (size_t)j * TTP);
            const __half2* hp = (const __half2*)&h;
            float2 f0 = __half22float2(hp[0]), f1 = __half22float2(hp[1]);
            float2 f2 = __half22float2(hp[2]), f3 = __half22float2(hp[3]);
            acc[j] += c0.x*f0.x + c0.y*f0.y + c0.z*f1.x + c0.w*f1.y
                    + c1.x*f2.x + c1.y*f2.y + c1.z*f3.x + c1.w*f3.y;
        }
    }
    for (int p = tid * 4; p < PPP; p += NTHR * 4) {
        float4 c = *(const float4*)&g_c2[p];
        const float* base = g_L2 + b0 * PPP + p;
        #pragma unroll
        for (int j = 0; j < 8; j++) {
            float4 x = *(const float4*)(base + j * PPP);
            acc[j] += c.x * x.x + c.y * x.y + c.z * x.z + c.w * x.w;
        }
    }

    __shared__ float red[8][8];   // [warp][j]
    #pragma unroll
    for (int j = 0; j < 8; j++) {
        float vsum = acc[j];
        #pragma unroll
        for (int o = 16; o; o >>= 1) vsum += __shfl_down_sync(0xffffffffu, vsum, o);
        if ((tid & 31) == 0) red[tid >> 5][j] = vsum;
    }
    __syncthreads();
    if (tid < 8) {
        float s = 0.f;
        #pragma unroll
        for (int wp = 0; wp < 8; wp++) s += red[wp][tid];
        out[b0 + tid] = s + g_lin[b0 + tid] + bias[0] + g_sumo;
    }
}

// ---------------------------------------------------------------------------
extern "C" void kernel_launch(void* const* d_in, const int* in_sizes, int n_in,
                              void* d_out, int out_size)
{
    const int*   feats  = (const int*)  d_in[0];
    const float* w      = (const float*)d_in[1];
    const float* v      = (const float*)d_in[2];
    const float* bias   = (const float*)d_in[3];
    const float* gamma2 = (const float*)d_in[4];
    const float* beta2  = (const float*)d_in[5];
    const float* gw2    = (const float*)d_in[6];
    const float* gamma3 = (const float*)d_in[7];
    const float* beta3  = (const float*)d_in[8];
    const float* gw3    = (const float*)d_in[9];
    const int*   rows   = (const int*)  d_in[10];
    const int*   cols   = (const int*)  d_in[11];
    const int*   i1     = (const int*)  d_in[12];
    const int*   i2     = (const int*)  d_in[13];
    const int*   i3     = (const int*)  d_in[14];
    float* out = (float*)d_out;

    pack_tri<<<TTP / NTHR, NTHR>>>(i1, i2, i3, rows, cols,
                                   gamma2, beta2, gw2, gamma3, beta3, gw3);
    compute_levels<<<BB, NTHR>>>(feats, w, v);
    stats_acc<<<dim3(NXB, BSPLIT), NTHR>>>();
    final_reduce<<<BB / 8, NTHR>>>(bias, out);
}

// round 17
// speedup vs baseline: 1.0435x; 1.0288x over previous
#include <cuda_runtime.h>
#include <cuda_fp16.h>

#define BB   1024
#define FF   39
#define KK   16
#define PP   741
#define PPP  768                      // padded pair stride
#define TT   9139
#define TTP  9216                     // padded triple stride (36*256)
#define SE   20                       // embedding row stride (floats)
#define NTHR 256
#define BSPLIT 16                     // batch split for stats
#define NXB  (TTP / 256 + PPP / 256)  // 39 x-blocks (36 L3 + 3 L2)
#define RBF  4                        // batch rows per CTA in final reduce
#define SCALE  65536.0f               // exact 2^16 scaling for fp16 storage

// ---- device-global scratch (no allocations allowed; zero-init at load,
//      padding regions are never written so they stay 0) ----
__device__ __align__(16) float  g_L2[BB * PPP];           // ~3.1 MB fp32
__device__ __align__(16) __half g_L3h[(size_t)BB * TTP];  // ~18.9 MB fp16 (x * 2^16)
__device__ float g_lin[BB];
__device__ __align__(16) float g_c2[PPP];    // pad stays 0
__device__ __align__(16) float g_c3[TTP];    // pad stays 0 (1/2^16 folded in)
__device__ float g_ps3[BSPLIT][TTP], g_pq3[BSPLIT][TTP];  // per-split partials
__device__ float g_ps2[BSPLIT][PPP], g_pq2[BSPLIT][PPP];
__device__ float g_g2[PP], g_b2p[PP], g_w2[PP];   // BN params permuted canonical
__device__ float g_g3[TT], g_b3p[TT], g_w3[TT];
__device__ int   g_cnt[NXB];                 // per-x-block completion counters
__device__ float g_sumo;

// ---------------------------------------------------------------------------
// Kernel A: per-batch-row gather + level2 (fp32) + level3 (fp16, x*2^16).
// Pair decode is ANALYTIC (no table). First 40 CTAs also do tail work:
// permute BN params to canonical order + reset counters (consumed only by
// the NEXT kernel, so intra-kernel ordering is irrelevant).
//   pair  (a,b2):   q  = b2(b2-1)/2 + a      (b2-major)
//   triple(a,b2,c): tc = C(c,3) + q
// ---------------------------------------------------------------------------
__global__ __launch_bounds__(NTHR) void compute_levels(
    const int*   __restrict__ feats,
    const float* __restrict__ w,
    const float* __restrict__ v,
    const int*   __restrict__ i1, const int* __restrict__ i2,
    const int*   __restrict__ i3,
    const int*   __restrict__ rows, const int* __restrict__ cols,
    const float* __restrict__ gamma2, const float* __restrict__ beta2,
    const float* __restrict__ gw2,
    const float* __restrict__ gamma3, const float* __restrict__ beta3,
    const float* __restrict__ gw3)
{
    __shared__ float sxv[FF * SE];
    __shared__ int   sidx[FF];

    const int b   = blockIdx.x;
    const int tid = threadIdx.x;

    if (tid < FF) sidx[tid] = feats[b * FF + tid];
    __syncthreads();

    for (int e = tid; e < FF * KK; e += NTHR) {
        int f = e >> 4, k = e & 15;
        sxv[f * SE + k] = v[(size_t)sidx[f] * KK + k];
    }
    if (tid < 32) {
        float s = 0.f;
        for (int f = tid; f < FF; f += 32) s += w[sidx[f]];
        #pragma unroll
        for (int o = 16; o; o >>= 1) s += __shfl_down_sync(0xffffffffu, s, o);
        if (tid == 0) g_lin[b] = s;
    }
    __syncthreads();

    __half* dst = g_L3h + (size_t)b * TTP;

    for (int q = tid; q < PP; q += NTHR) {
        // analytic pair decode with exact integer correction
        int b2 = (int)((1.0f + sqrtf(8.0f * (float)q + 1.0f)) * 0.5f);
        while (b2 * (b2 - 1) / 2 > q)  b2--;
        while (b2 * (b2 + 1) / 2 <= q) b2++;
        int a = q - b2 * (b2 - 1) / 2;

        const float4* ea = (const float4*)&sxv[a * SE];
        const float4* eb = (const float4*)&sxv[b2 * SE];

        float4 p0, p1, p2, p3;
        {
            float4 x, y;
            x = ea[0]; y = eb[0];
            p0.x = x.x*y.x; p0.y = x.y*y.y; p0.z = x.z*y.z; p0.w = x.w*y.w;
            x = ea[1]; y = eb[1];
            p1.x = x.x*y.x; p1.y = x.y*y.y; p1.z = x.z*y.z; p1.w = x.w*y.w;
            x = ea[2]; y = eb[2];
            p2.x = x.x*y.x; p2.y = x.y*y.y; p2.z = x.z*y.z; p2.w = x.w*y.w;
            x = ea[3]; y = eb[3];
            p3.x = x.x*y.x; p3.y = x.y*y.y; p3.z = x.z*y.z; p3.w = x.w*y.w;
        }
        g_L2[b * PPP + q] = (p0.x+p0.y+p0.z+p0.w) + (p1.x+p1.y+p1.z+p1.w)
                          + (p2.x+p2.y+p2.z+p2.w) + (p3.x+p3.y+p3.z+p3.w);

        int c0   = b2 + 1;
        int base = (c0 * (c0 - 1) * (c0 - 2)) / 6;
        int inc  = (c0 * (c0 - 1)) / 2;
        for (int c = c0; c < FF; c++) {
            const float4* ec = (const float4*)&sxv[c * SE];   // broadcast
            float4 e0 = ec[0], e1 = ec[1], e2 = ec[2], e3 = ec[3];
            float s0 = p0.x*e0.x + p0.y*e0.y + p0.z*e0.z + p0.w*e0.w;
            float s1 = p1.x*e1.x + p1.y*e1.y + p1.z*e1.z + p1.w*e1.w;
            float s2 = p2.x*e2.x + p2.y*e2.y + p2.z*e2.z + p2.w*e2.w;
            float s3 = p3.x*e3.x + p3.y*e3.y + p3.z*e3.z + p3.w*e3.w;
            dst[base + q] = __float2half_rn(((s0 + s1) + (s2 + s3)) * SCALE);
            base += inc;
            inc  += c;
        }
    }

    // ---- tail work (replaces pack_tri kernel) ----
    if (b < 36) {
        int t = b * 256 + tid;
        if (t < TT) {
            int aa = i1[t], bb = i2[t], cc = i3[t];
            int tc = (cc * (cc - 1) * (cc - 2)) / 6 + (bb * (bb - 1)) / 2 + aa;
            g_g3[tc]  = gamma3[t];
            g_b3p[tc] = beta3[t];
            g_w3[tc]  = gw3[t];
        }
    } else if (b < 39) {
        int t = (b - 36) * 256 + tid;
        if (t < PP) {
            int r = rows[t], cl = cols[t];            // r > cl
            int qq = (r * (r - 1)) / 2 + cl;
            g_g2[qq]  = gamma2[t];
            g_b2p[qq] = beta2[t];
            g_w2[qq]  = gw2[t];
        }
    } else if (b == 39) {
        if (tid < NXB) g_cnt[tid] = 0;
        if (tid == 0)  g_sumo = 0.f;
    }
}

// ---------------------------------------------------------------------------
// Kernel B: fused batch-split column stats + LAST-CTA finalize per x-block.
// grid (NXB, BSPLIT). Each tx owns 8 consecutive columns; 64 rows per split.
// The 16th CTA to finish an x-block sums the 16 partials and emits c/o.
// ---------------------------------------------------------------------------
__global__ __launch_bounds__(NTHR) void stats_acc()
{
    __shared__ float shs[8][NTHR], shq[8][NTHR];
    __shared__ int   s_last;
    const int tx = threadIdx.x & 31;
    const int ty = threadIdx.x >> 5;
    const int split = blockIdx.y;
    const int b0 = split * (BB / BSPLIT);     // 64 rows
    const bool isL3 = blockIdx.x < TTP / 256;

    float s[8], q[8];
    #pragma unroll
    for (int e = 0; e < 8; e++) { s[e] = 0.f; q[e] = 0.f; }

    if (isL3) {
        const int t0 = blockIdx.x * 256 + tx * 8;
        for (int i = ty; i < BB / BSPLIT; i += 8) {
            uint4 h = *(const uint4*)(g_L3h + (size_t)(b0 + i) * TTP + t0);
            const __half2* hp = (const __half2*)&h;
            #pragma unroll
            for (int e = 0; e < 4; e++) {
                float2 f = __half22float2(hp[e]);
                s[2*e]   += f.x; q[2*e]   += f.x * f.x;
                s[2*e+1] += f.y; q[2*e+1] += f.y * f.y;
            }
        }
        #pragma unroll
        for (int e = 0; e < 8; e++) { shs[ty][tx*8+e] = s[e]; shq[ty][tx*8+e] = q[e]; }
        __syncthreads();
        int col = threadIdx.x;
        float S = 0.f, Q = 0.f;
        #pragma unroll
        for (int j = 0; j < 8; j++) { S += shs[j][col]; Q += shq[j][col]; }
        g_ps3[split][blockIdx.x * 256 + col] = S;
        g_pq3[split][blockIdx.x * 256 + col] = Q;
    } else {
        const int p0 = (blockIdx.x - TTP / 256) * 256 + tx * 8;
        for (int i = ty; i < BB / BSPLIT; i += 8) {
            const float4* xp = (const float4*)(g_L2 + (b0 + i) * PPP + p0);
            float4 x = xp[0], y = xp[1];
            s[0]+=x.x; q[0]+=x.x*x.x;  s[1]+=x.y; q[1]+=x.y*x.y;
            s[2]+=x.z; q[2]+=x.z*x.z;  s[3]+=x.w; q[3]+=x.w*x.w;
            s[4]+=y.x; q[4]+=y.x*y.x;  s[5]+=y.y; q[5]+=y.y*y.y;
            s[6]+=y.z; q[6]+=y.z*y.z;  s[7]+=y.w; q[7]+=y.w*y.w;
        }
        #pragma unroll
        for (int e = 0; e < 8; e++) { shs[ty][tx*8+e] = s[e]; shq[ty][tx*8+e] = q[e]; }
        __syncthreads();
        int col = threadIdx.x;
        float S = 0.f, Q = 0.f;
        #pragma unroll
        for (int j = 0; j < 8; j++) { S += shs[j][col]; Q += shq[j][col]; }
        g_ps2[split][(blockIdx.x - TTP / 256) * 256 + col] = S;
        g_pq2[split][(blockIdx.x - TTP / 256) * 256 + col] = Q;
    }

    // ---- last-CTA-done finalize for this x-block ----
    __threadfence();
    if (threadIdx.x == 0)
        s_last = (atomicAdd(&g_cnt[blockIdx.x], 1) == BSPLIT - 1);
    __syncthreads();
    if (!s_last) return;
    __threadfence();   // make other CTAs' partials visible

    float osum = 0.f;
    if (isL3) {
        const int t = blockIdx.x * 256 + threadIdx.x;
        float S = 0.f, Q = 0.f;
        #pragma unroll
        for (int sp = 0; sp < BSPLIT; sp++) { S += g_ps3[sp][t]; Q += g_pq3[sp][t]; }
        if (t < TT) {
            float mean_s = S * (1.0f / BB);                       // scaled mean
            float var_s  = Q * (1.0f / BB) - mean_s * mean_s;     // scaled^2 var
            float inv    = rsqrtf(var_s * (1.0f / (SCALE * SCALE)) + 1e-3f);
            float c_true = g_g3[t] * g_w3[t] * inv;
            float c3p    = c_true * (1.0f / SCALE);
            g_c3[t] = c3p;
            osum = g_b3p[t] * g_w3[t] - c3p * mean_s;             // c_true*mean_true
        }
    } else {
        const int p = (blockIdx.x - TTP / 256) * 256 + threadIdx.x;
        float S = 0.f, Q = 0.f;
        #pragma unroll
        for (int sp = 0; sp < BSPLIT; sp++) { S += g_ps2[sp][p]; Q += g_pq2[sp][p]; }
        if (p < PP) {
            float mean = S * (1.0f / BB);
            float var  = Q * (1.0f / BB) - mean * mean;
            float inv  = rsqrtf(var + 1e-3f);
            float cc   = g_g2[p] * g_w2[p] * inv;
            g_c2[p] = cc;
            osum = g_b2p[p] * g_w2[p] - cc * mean;
        }
    }
    #pragma unroll
    for (int o = 16; o; o >>= 1) osum += __shfl_down_sync(0xffffffffu, osum, o);
    if ((threadIdx.x & 31) == 0) shs[0][threadIdx.x >> 5] = osum;
    __syncthreads();
    if (threadIdx.x == 0) {
        float t2 = 0.f;
        #pragma unroll
        for (int j = 0; j < 8; j++) t2 += shs[0][j];
        atomicAdd(&g_sumo, t2);
    }
}

// ---------------------------------------------------------------------------
// Kernel C: weighted reductions + epilogue. grid 256, RBF=4 b-rows per CTA
// (2 CTAs resident per SM -> 2x latency hiding vs 128-CTA version).
// Pad columns: c3=0 and L3h=0 -> guard-free half8/float4 loads.
// ---------------------------------------------------------------------------
__global__ __launch_bounds__(NTHR) void final_reduce(
    const float* __restrict__ bias, float* __restrict__ out)
{
    const int b0  = blockIdx.x * RBF;
    const int tid = threadIdx.x;
    float acc[RBF] = {0.f, 0.f, 0.f, 0.f};

    for (int t = tid * 8; t < TTP; t += NTHR * 8) {
        float4 c0 = *(const float4*)&g_c3[t];
        float4 c1 = *(const float4*)&g_c3[t + 4];
        const __half* base = g_L3h + (size_t)b0 * TTP + t;
        #pragma unroll
        for (int j = 0; j < RBF; j++) {
            uint4 h = *(const uint4*)(base + (size_t)j * TTP);
            const __half2* hp = (const __half2*)&h;
            float2 f0 = __half22float2(hp[0]), f1 = __half22float2(hp[1]);
            float2 f2 = __half22float2(hp[2]), f3 = __half22float2(hp[3]);
            acc[j] += c0.x*f0.x + c0.y*f0.y + c0.z*f1.x + c0.w*f1.y
                    + c1.x*f2.x + c1.y*f2.y + c1.z*f3.x + c1.w*f3.y;
        }
    }
    for (int p = tid * 4; p < PPP; p += NTHR * 4) {
        float4 c = *(const float4*)&g_c2[p];
        const float* base = g_L2 + b0 * PPP + p;
        #pragma unroll
        for (int j = 0; j < RBF; j++) {
            float4 x = *(const float4*)(base + j * PPP);
            acc[j] += c.x * x.x + c.y * x.y + c.z * x.z + c.w * x.w;
        }
    }

    __shared__ float red[8][RBF];   // [warp][j]
    #pragma unroll
    for (int j = 0; j < RBF; j++) {
        float vsum = acc[j];
        #pragma unroll
        for (int o = 16; o; o >>= 1) vsum += __shfl_down_sync(0xffffffffu, vsum, o);
        if ((tid & 31) == 0) red[tid >> 5][j] = vsum;
    }
    __syncthreads();
    if (tid < RBF) {
        float s = 0.f;
        #pragma unroll
        for (int wp = 0; wp < 8; wp++) s += red[wp][tid];
        out[b0 + tid] = s + g_lin[b0 + tid] + bias[0] + g_sumo;
    }
}

// ---------------------------------------------------------------------------
extern "C" void kernel_launch(void* const* d_in, const int* in_sizes, int n_in,
                              void* d_out, int out_size)
{
    const int*   feats  = (const int*)  d_in[0];
    const float* w      = (const float*)d_in[1];
    const float* v      = (const float*)d_in[2];
    const float* bias   = (const float*)d_in[3];
    const float* gamma2 = (const float*)d_in[4];
    const float* beta2  = (const float*)d_in[5];
    const float* gw2    = (const float*)d_in[6];
    const float* gamma3 = (const float*)d_in[7];
    const float* beta3  = (const float*)d_in[8];
    const float* gw3    = (const float*)d_in[9];
    const int*   rows   = (const int*)  d_in[10];
    const int*   cols   = (const int*)  d_in[11];
    const int*   i1     = (const int*)  d_in[12];
    const int*   i2     = (const int*)  d_in[13];
    const int*   i3     = (const int*)  d_in[14];
    float* out = (float*)d_out;

    compute_levels<<<BB, NTHR>>>(feats, w, v, i1, i2, i3, rows, cols,
                                 gamma2, beta2, gw2, gamma3, beta3, gw3);
    stats_acc<<<dim3(NXB, BSPLIT), NTHR>>>();
    final_reduce<<<BB / RBF, NTHR>>>(bias, out);
}